// round 2
// baseline (speedup 1.0000x reference)
#include <cuda_runtime.h>
#include <mma.h>

using namespace nvcuda;

// Problem constants (fixed by the dataset)
constexpr int kE = 32;     // experts
constexpr int kD = 2048;   // hidden
constexpr int kF = 768;    // intermediate
constexpr int kT = 2048;   // tokens (B*S)

constexpr int BM = 128;
constexpr int BN = 128;
constexpr int BK = 16;

// Scratch: gated activations for all experts, fp32. [E][T][F] = 201 MB.
__device__ float g_gated[(size_t)kE * kT * kF];

using FragA = wmma::fragment<wmma::matrix_a, 16, 16, 8, wmma::precision::tf32, wmma::row_major>;
using FragB = wmma::fragment<wmma::matrix_b, 16, 16, 8, wmma::precision::tf32, wmma::row_major>;
using FragC = wmma::fragment<wmma::accumulator, 16, 16, 8, float>;

// Round a float4 to tf32 (RN) once, before it ever hits smem.
__device__ __forceinline__ float4 tf32x4(float4 v) {
    v.x = wmma::__float_to_tf32(v.x);
    v.y = wmma::__float_to_tf32(v.y);
    v.z = wmma::__float_to_tf32(v.z);
    v.w = wmma::__float_to_tf32(v.w);
    return v;
}

// Shared-memory stage geometry (floats)
constexpr int A_LD  = 20;                 // 16 + pad
constexpr int B_LD  = 132;                // 128 + pad
constexpr int A_SZ  = BM * A_LD;          // 2560
constexpr int B_SZ  = BK * B_LD;          // 2112
constexpr int S1    = A_SZ + 2 * B_SZ;    // gemm1 stage: A + Bg + Bu = 6784
constexpr int S2    = A_SZ + B_SZ;        // gemm2 stage: A + B      = 4672
constexpr int SMEM1_BYTES = 2 * S1 * 4;   // 54272
constexpr int SMEM2_BYTES = 2 * S2 * 4;   // 37376

// ---------------------------------------------------------------------------
// GEMM1: gated[e][t][f] = up * silu(gate),
//   gate = X(T,D) @ Wgu[e](D, 0:F), up = X @ Wgu[e](D, F:2F)
// Grid: (T/128, F/128, E). Block: 512 threads = 16 warps (4x4 warp grid).
// Double-buffered smem, tf32 pre-rounded at smem store, one barrier/iter.
// ---------------------------------------------------------------------------
__global__ __launch_bounds__(512, 1)
void moe_gemm1(const float* __restrict__ X,     // [T][D]
               const float* __restrict__ W)     // [E][D][2F]
{
    extern __shared__ float sm[];
    float* Asb[2] = { sm,            sm + S1 };
    float* Bgb[2] = { sm + A_SZ,     sm + S1 + A_SZ };
    float* Bub[2] = { sm + A_SZ + B_SZ, sm + S1 + A_SZ + B_SZ };

    const int m0 = blockIdx.x * BM;
    const int n0 = blockIdx.y * BN;
    const int e  = blockIdx.z;
    const float* We = W + (size_t)e * kD * (2 * kF);

    const int tid  = threadIdx.x;
    const int warp = tid >> 5;
    const int wm   = (warp >> 2) * 32;
    const int wn   = (warp & 3) * 32;

    // Load assignments: A tile 128x16 -> 1 float4/thread; each B tile 16x128 -> 1 float4/thread
    const int ar = tid >> 2;          // 0..127
    const int ac = (tid & 3) * 4;     // 0,4,8,12
    const int br = tid >> 5;          // 0..15
    const int bc = (tid & 31) * 4;    // 0..124

    FragC accg[2][2], accu[2][2];
#pragma unroll
    for (int i = 0; i < 2; i++)
#pragma unroll
        for (int j = 0; j < 2; j++) {
            wmma::fill_fragment(accg[i][j], 0.0f);
            wmma::fill_fragment(accu[i][j], 0.0f);
        }

    const float* aPtr  = X  + (size_t)(m0 + ar) * kD + ac;
    const float* bgPtr = We + (size_t)br * (2 * kF) + n0 + bc;
    const float* buPtr = bgPtr + kF;

    // Stage 0: load, round, store
    {
        float4 a  = tf32x4(*(const float4*)aPtr);
        float4 bg = tf32x4(*(const float4*)bgPtr);
        float4 bu = tf32x4(*(const float4*)buPtr);
        *(float4*)&Asb[0][ar * A_LD + ac] = a;
        *(float4*)&Bgb[0][br * B_LD + bc] = bg;
        *(float4*)&Bub[0][br * B_LD + bc] = bu;
    }
    __syncthreads();

    int cur = 0;
    for (int k0 = 0; k0 < kD; k0 += BK) {
        const int kn = k0 + BK;
        const bool has = kn < kD;

        // Issue next-stage global loads first (latency hides under MMAs)
        float4 aN, bgN, buN;
        if (has) {
            aN  = *(const float4*)(aPtr + kn);
            bgN = *(const float4*)(bgPtr + (size_t)kn * (2 * kF));
            buN = *(const float4*)(buPtr + (size_t)kn * (2 * kF));
        }

        const float* As = Asb[cur];
        const float* Bg = Bgb[cur];
        const float* Bu = Bub[cur];
#pragma unroll
        for (int kk = 0; kk < BK; kk += 8) {
            FragA a[2];
            FragB bg[2], bu[2];
#pragma unroll
            for (int i = 0; i < 2; i++)
                wmma::load_matrix_sync(a[i], &As[(wm + i * 16) * A_LD + kk], A_LD);
#pragma unroll
            for (int j = 0; j < 2; j++) {
                wmma::load_matrix_sync(bg[j], &Bg[kk * B_LD + wn + j * 16], B_LD);
                wmma::load_matrix_sync(bu[j], &Bu[kk * B_LD + wn + j * 16], B_LD);
            }
#pragma unroll
            for (int i = 0; i < 2; i++)
#pragma unroll
                for (int j = 0; j < 2; j++) {
                    wmma::mma_sync(accg[i][j], a[i], bg[j], accg[i][j]);
                    wmma::mma_sync(accu[i][j], a[i], bu[j], accu[i][j]);
                }
        }

        if (has) {
            const int nxt = cur ^ 1;
            *(float4*)&Asb[nxt][ar * A_LD + ac] = tf32x4(aN);
            *(float4*)&Bgb[nxt][br * B_LD + bc] = tf32x4(bgN);
            *(float4*)&Bub[nxt][br * B_LD + bc] = tf32x4(buN);
        }
        __syncthreads();
        cur ^= 1;
    }

    // Epilogue: gated = up * silu(gate)
    float* Gp = g_gated + (size_t)e * kT * kF;
#pragma unroll
    for (int i = 0; i < 2; i++)
#pragma unroll
        for (int j = 0; j < 2; j++) {
#pragma unroll
            for (int q = 0; q < accg[i][j].num_elements; q++) {
                const float gt = accg[i][j].x[q];
                const float up = accu[i][j].x[q];
                const float s  = gt / (1.0f + __expf(-gt));
                accg[i][j].x[q] = up * s;
            }
            wmma::store_matrix_sync(
                Gp + (size_t)(m0 + wm + i * 16) * kF + (n0 + wn + j * 16),
                accg[i][j], kF, wmma::mem_row_major);
        }
}

// ---------------------------------------------------------------------------
// GEMM2: out[t][d] = sum_e w[t,e] * (gated[e][t][:] @ Wd[e][:, d])
// Routing weight folded into the A-tile smem load. K = 32*768 = 24576.
// Grid: (T/128, D/128). Block: 512 threads. Same double-buffer scheme.
// ---------------------------------------------------------------------------
__global__ __launch_bounds__(512, 1)
void moe_gemm2(const float* __restrict__ Wd,   // [E][F][D]
               const float* __restrict__ RW,   // [T][E]
               float* __restrict__ Out)        // [T][D]
{
    extern __shared__ float sm[];
    float* Asb[2] = { sm,        sm + S2 };
    float* Bsb[2] = { sm + A_SZ, sm + S2 + A_SZ };

    const int m0 = blockIdx.x * BM;
    const int n0 = blockIdx.y * BN;

    const int tid  = threadIdx.x;
    const int warp = tid >> 5;
    const int wm   = (warp >> 2) * 32;
    const int wn   = (warp & 3) * 32;

    const int ar = tid >> 2;
    const int ac = (tid & 3) * 4;
    const int br = tid >> 5;
    const int bc = (tid & 31) * 4;

    FragC acc[2][2];
#pragma unroll
    for (int i = 0; i < 2; i++)
#pragma unroll
        for (int j = 0; j < 2; j++)
            wmma::fill_fragment(acc[i][j], 0.0f);

    constexpr int KT = kE * kF;   // 24576
    const float* rwRow = RW + (size_t)(m0 + ar) * kE;

    // Stage 0 (expert 0, kin 0)
    {
        const float w = __ldg(rwRow);
        float4 a = *(const float4*)(g_gated + (size_t)(m0 + ar) * kF + ac);
        a.x *= w; a.y *= w; a.z *= w; a.w *= w;
        float4 b = *(const float4*)(Wd + (size_t)br * kD + n0 + bc);
        *(float4*)&Asb[0][ar * A_LD + ac] = tf32x4(a);
        *(float4*)&Bsb[0][br * B_LD + bc] = tf32x4(b);
    }
    __syncthreads();

    int cur = 0;
    for (int kt = 0; kt < KT; kt += BK) {
        const int kn = kt + BK;
        const bool has = kn < KT;

        float4 aN, bN;
        float wN = 0.0f;
        if (has) {
            const int en  = kn / kF;             // kF % BK == 0, tiles never straddle experts
            const int kin = kn - en * kF;
            wN = __ldg(rwRow + en);
            aN = *(const float4*)(g_gated + ((size_t)en * kT + (m0 + ar)) * kF + kin + ac);
            bN = *(const float4*)(Wd + ((size_t)en * kF + (kin + br)) * kD + n0 + bc);
        }

        const float* As = Asb[cur];
        const float* Bs = Bsb[cur];
#pragma unroll
        for (int kk = 0; kk < BK; kk += 8) {
            FragA a[2];
            FragB b[2];
#pragma unroll
            for (int i = 0; i < 2; i++)
                wmma::load_matrix_sync(a[i], &As[(wm + i * 16) * A_LD + kk], A_LD);
#pragma unroll
            for (int j = 0; j < 2; j++)
                wmma::load_matrix_sync(b[j], &Bs[kk * B_LD + wn + j * 16], B_LD);
#pragma unroll
            for (int i = 0; i < 2; i++)
#pragma unroll
                for (int j = 0; j < 2; j++)
                    wmma::mma_sync(acc[i][j], a[i], b[j], acc[i][j]);
        }

        if (has) {
            const int nxt = cur ^ 1;
            aN.x *= wN; aN.y *= wN; aN.z *= wN; aN.w *= wN;
            *(float4*)&Asb[nxt][ar * A_LD + ac] = tf32x4(aN);
            *(float4*)&Bsb[nxt][br * B_LD + bc] = tf32x4(bN);
        }
        __syncthreads();
        cur ^= 1;
    }

#pragma unroll
    for (int i = 0; i < 2; i++)
#pragma unroll
        for (int j = 0; j < 2; j++)
            wmma::store_matrix_sync(
                Out + (size_t)(m0 + wm + i * 16) * kD + (n0 + wn + j * 16),
                acc[i][j], kD, wmma::mem_row_major);
}

// ---------------------------------------------------------------------------
// kernel_launch
// Inputs (metadata order):
//   0: hidden_states   fp32 [B,S,D] = [T,D]
//   1: routing_weights fp32 [T,E]
//   2: router_indices  int32 [T,TOPK]   (UNUSED by the reference)
//   3: gate_up_proj    fp32 [E,D,2F]
//   4: down_proj       fp32 [E,F,D]
// Output: fp32 [T,D]
// ---------------------------------------------------------------------------
extern "C" void kernel_launch(void* const* d_in, const int* in_sizes, int n_in,
                              void* d_out, int out_size)
{
    const float* X   = (const float*)d_in[0];
    const float* RW  = (const float*)d_in[1];
    const float* Wgu = (const float*)d_in[3];
    const float* Wdn = (const float*)d_in[4];
    float* Out = (float*)d_out;

    // Opt-in to >48KB dynamic smem (idempotent; not a stream op, capture-safe).
    cudaFuncSetAttribute(moe_gemm1, cudaFuncAttributeMaxDynamicSharedMemorySize, SMEM1_BYTES);
    cudaFuncSetAttribute(moe_gemm2, cudaFuncAttributeMaxDynamicSharedMemorySize, SMEM2_BYTES);

    dim3 g1(kT / BM, kF / BN, kE);   // (16, 6, 32)
    moe_gemm1<<<g1, 512, SMEM1_BYTES>>>(X, Wgu);

    dim3 g2(kT / BM, kD / BN);       // (16, 16)
    moe_gemm2<<<g2, 512, SMEM2_BYTES>>>(Wdn, RW, Out);
}

// round 5
// speedup vs baseline: 1.8164x; 1.8164x over previous
#include <cuda_runtime.h>
#include <cstdint>

// ---------------------------------------------------------------------------
// Problem constants
// ---------------------------------------------------------------------------
constexpr int kE = 32, kD = 2048, kF = 768, kT = 2048;
constexpr int k2F = 2 * kF;                       // 1536

constexpr int BM = 128, BN = 128, BK = 32;
constexpr int STAGES = 3;

// smem geometry (floats). Strides chosen so fragment gathers are conflict-free:
// A stride 36 (=4 mod 32), B stride 136 (=8 mod 32).
constexpr int A_LD = 36, B_LD = 136;
constexpr int A_F = BM * A_LD;                    // 4608
constexpr int B_F = BK * B_LD;                    // 4352
constexpr int STAGE_F = A_F + B_F;                // 8960 floats = 35840 B
constexpr int SMEM_BYTES = STAGES * STAGE_F * 4;  // 107520 B

// Scratch (device globals; no allocations allowed)
__device__ float g_gateup[(size_t)kE * kT * k2F]; // [E][T][2F]  402 MB
__device__ float g_gated [(size_t)kE * kT * kF];  // [E][T][F]   201 MB

// ---------------------------------------------------------------------------
// helpers
// ---------------------------------------------------------------------------
__device__ __forceinline__ uint32_t smem_u32(const void* p) {
    uint32_t a;
    asm("{ .reg .u64 t; cvta.to.shared.u64 t, %1; cvt.u32.u64 %0, t; }"
        : "=r"(a) : "l"(p));
    return a;
}
__device__ __forceinline__ uint32_t f2tf(float x) {
    uint32_t r; asm("cvt.rna.tf32.f32 %0, %1;" : "=r"(r) : "f"(x)); return r;
}
__device__ __forceinline__ void cp16(uint32_t saddr, const float* g) {
    asm volatile("cp.async.cg.shared.global [%0], [%1], 16;" :: "r"(saddr), "l"(g));
}
#define CP_COMMIT() asm volatile("cp.async.commit_group;" ::: "memory")
#define CP_WAIT1()  asm volatile("cp.async.wait_group 1;" ::: "memory")

__device__ __forceinline__ void mma8(float* c, const uint32_t* a, const uint32_t* b) {
    asm volatile(
        "mma.sync.aligned.m16n8k8.row.col.f32.tf32.tf32.f32 "
        "{%0,%1,%2,%3}, {%4,%5,%6,%7}, {%8,%9}, {%0,%1,%2,%3};"
        : "+f"(c[0]), "+f"(c[1]), "+f"(c[2]), "+f"(c[3])
        : "r"(a[0]), "r"(a[1]), "r"(a[2]), "r"(a[3]), "r"(b[0]), "r"(b[1]));
}

// ---------------------------------------------------------------------------
// Shared GEMM core: C[BMxBN] tile, 8 warps in 2(m) x 4(n), warp tile 64x32.
// A smem [BM][A_LD] row-major (k contiguous); B smem [BK][B_LD] (n contiguous).
// ---------------------------------------------------------------------------
struct WarpCtx {
    int wm, wn, g, tig;
};

__device__ __forceinline__ void compute_stage(const float* As, const float* Bs,
                                              const WarpCtx& w, float c[4][4][4]) {
#pragma unroll
    for (int kk = 0; kk < BK; kk += 8) {
        uint32_t a[4][4];
#pragma unroll
        for (int mi = 0; mi < 4; ++mi) {
            const int base = (w.wm + 16 * mi + w.g) * A_LD + kk + w.tig;
            a[mi][0] = f2tf(As[base]);
            a[mi][1] = f2tf(As[base + 8 * A_LD]);
            a[mi][2] = f2tf(As[base + 4]);
            a[mi][3] = f2tf(As[base + 8 * A_LD + 4]);
        }
        uint32_t b[4][2];
#pragma unroll
        for (int nj = 0; nj < 4; ++nj) {
            const int col = w.wn + 8 * nj + w.g;
            b[nj][0] = f2tf(Bs[(kk + w.tig) * B_LD + col]);
            b[nj][1] = f2tf(Bs[(kk + w.tig + 4) * B_LD + col]);
        }
#pragma unroll
        for (int mi = 0; mi < 4; ++mi)
#pragma unroll
            for (int nj = 0; nj < 4; ++nj)
                mma8(c[mi][nj], a[mi], b[nj]);
    }
}

// ---------------------------------------------------------------------------
// GEMM1: g_gateup[e][t][n] = X[t][:] @ Wgu[e][:][n], n in [0,2F)
// grid (T/128, 2F/128 = 12, E), 256 threads
// ---------------------------------------------------------------------------
__global__ __launch_bounds__(256, 2)
void moe_gemm1(const float* __restrict__ X, const float* __restrict__ Wgu) {
    extern __shared__ float sm[];
    const int tid = threadIdx.x;
    const int m0 = blockIdx.x * BM, n0 = blockIdx.y * BN, e = blockIdx.z;
    const float* We = Wgu + (size_t)e * kD * k2F;

    const uint32_t sb = smem_u32(sm);

    // cp.async assignments: A 128 rows x 8 chunks (2 thr/row, 4 chunks each),
    //                       B 32 rows x 32 chunks (8 thr/row, 4 chunks each)
    const int arow = tid >> 1, acol = (tid & 1) * 16;   // floats
    const int brow = tid >> 3, bcol = (tid & 7) * 16;

    const float* gA = X + (size_t)(m0 + arow) * kD + acol;
    const float* gB = We + (size_t)brow * k2F + n0 + bcol;

    const WarpCtx w = { ((tid >> 5) >> 2) * 64, ((tid >> 5) & 3) * 32,
                        (tid & 31) >> 2, tid & 3 };

    float c[4][4][4];
#pragma unroll
    for (int i = 0; i < 4; ++i)
#pragma unroll
        for (int j = 0; j < 4; ++j)
#pragma unroll
            for (int q = 0; q < 4; ++q) c[i][j][q] = 0.0f;

    constexpr int ITERS = kD / BK;   // 64

    auto issue = [&](int it) {
        const int s = it % STAGES;
        const uint32_t sa = sb + (s * STAGE_F) * 4;
        const uint32_t sbb = sa + A_F * 4;
        const int k0 = it * BK;
#pragma unroll
        for (int q = 0; q < 4; ++q)
            cp16(sa + (arow * A_LD + acol + q * 4) * 4, gA + k0 + q * 4);
#pragma unroll
        for (int q = 0; q < 4; ++q)
            cp16(sbb + (brow * B_LD + bcol + q * 4) * 4,
                 gB + (size_t)k0 * k2F + q * 4);
    };

    issue(0); CP_COMMIT();
    issue(1); CP_COMMIT();

    for (int it = 0; it < ITERS; ++it) {
        CP_WAIT1();
        __syncthreads();
        if (it + 2 < ITERS) issue(it + 2);
        CP_COMMIT();
        const float* As = sm + (it % STAGES) * STAGE_F;
        compute_stage(As, As + A_F, w, c);
        __syncthreads();
    }

    // epilogue: write raw gate_up
    float* Cp = g_gateup + ((size_t)e * kT + m0) * k2F + n0;
#pragma unroll
    for (int mi = 0; mi < 4; ++mi)
#pragma unroll
        for (int nj = 0; nj < 4; ++nj) {
            const int r0 = w.wm + 16 * mi + w.g;
            const int cc = w.wn + 8 * nj + 2 * w.tig;
            *(float2*)(Cp + (size_t)r0 * k2F + cc) = make_float2(c[mi][nj][0], c[mi][nj][1]);
            *(float2*)(Cp + (size_t)(r0 + 8) * k2F + cc) = make_float2(c[mi][nj][2], c[mi][nj][3]);
        }
}

// ---------------------------------------------------------------------------
// K2: g_gated[e][t][f] = rw[t][e] * up * silu(gate)
// ---------------------------------------------------------------------------
__global__ __launch_bounds__(256)
void moe_act(const float* __restrict__ RW) {
    constexpr int NF4 = kF / 4;                        // 192
    const size_t idx = (size_t)blockIdx.x * 256 + threadIdx.x;
    const int f4 = (int)(idx % NF4) * 4;
    const size_t rest = idx / NF4;
    const int t = (int)(rest % kT);
    const int e = (int)(rest / kT);

    const float rw = RW[(size_t)t * kE + e];
    const float* base = g_gateup + ((size_t)e * kT + t) * k2F;
    const float4 gt = *(const float4*)(base + f4);
    const float4 up = *(const float4*)(base + kF + f4);
    float4 o;
    o.x = rw * up.x * (gt.x / (1.0f + __expf(-gt.x)));
    o.y = rw * up.y * (gt.y / (1.0f + __expf(-gt.y)));
    o.z = rw * up.z * (gt.z / (1.0f + __expf(-gt.z)));
    o.w = rw * up.w * (gt.w / (1.0f + __expf(-gt.w)));
    *(float4*)(g_gated + ((size_t)e * kT + t) * kF + f4) = o;
}

// ---------------------------------------------------------------------------
// GEMM2: Out[t][d] = sum_{e,f} g_gated[e][t][f] * Wd[e][f][d]
// grid (T/128, D/128), 256 threads, K = E*F = 24576 (768 iters)
// ---------------------------------------------------------------------------
__global__ __launch_bounds__(256, 2)
void moe_gemm2(const float* __restrict__ Wd, float* __restrict__ Out) {
    extern __shared__ float sm[];
    const int tid = threadIdx.x;
    const int m0 = blockIdx.x * BM, n0 = blockIdx.y * BN;

    const uint32_t sb = smem_u32(sm);

    const int arow = tid >> 1, acol = (tid & 1) * 16;
    const int brow = tid >> 3, bcol = (tid & 7) * 16;

    const WarpCtx w = { ((tid >> 5) >> 2) * 64, ((tid >> 5) & 3) * 32,
                        (tid & 31) >> 2, tid & 3 };

    float c[4][4][4];
#pragma unroll
    for (int i = 0; i < 4; ++i)
#pragma unroll
        for (int j = 0; j < 4; ++j)
#pragma unroll
            for (int q = 0; q < 4; ++q) c[i][j][q] = 0.0f;

    constexpr int ITERS = kE * kF / BK;   // 768
    constexpr int IPEX  = kF / BK;        // 24

    auto issue = [&](int it) {
        const int s = it % STAGES;
        const uint32_t sa = sb + (s * STAGE_F) * 4;
        const uint32_t sbb = sa + A_F * 4;
        const int e   = it / IPEX;
        const int kin = (it - e * IPEX) * BK;
        const float* gA = g_gated + ((size_t)e * kT + m0 + arow) * kF + kin + acol;
        const float* gB = Wd + ((size_t)e * kF + kin + brow) * kD + n0 + bcol;
#pragma unroll
        for (int q = 0; q < 4; ++q)
            cp16(sa + (arow * A_LD + acol + q * 4) * 4, gA + q * 4);
#pragma unroll
        for (int q = 0; q < 4; ++q)
            cp16(sbb + (brow * B_LD + bcol + q * 4) * 4, gB + q * 4);
    };

    issue(0); CP_COMMIT();
    issue(1); CP_COMMIT();

    for (int it = 0; it < ITERS; ++it) {
        CP_WAIT1();
        __syncthreads();
        if (it + 2 < ITERS) issue(it + 2);
        CP_COMMIT();
        const float* As = sm + (it % STAGES) * STAGE_F;
        compute_stage(As, As + A_F, w, c);
        __syncthreads();
    }

    float* Cp = Out + (size_t)m0 * kD + n0;
#pragma unroll
    for (int mi = 0; mi < 4; ++mi)
#pragma unroll
        for (int nj = 0; nj < 4; ++nj) {
            const int r0 = w.wm + 16 * mi + w.g;
            const int cc = w.wn + 8 * nj + 2 * w.tig;
            *(float2*)(Cp + (size_t)r0 * kD + cc) = make_float2(c[mi][nj][0], c[mi][nj][1]);
            *(float2*)(Cp + (size_t)(r0 + 8) * kD + cc) = make_float2(c[mi][nj][2], c[mi][nj][3]);
        }
}

// ---------------------------------------------------------------------------
// kernel_launch
//   0: hidden_states fp32 [T,D]   1: routing_weights fp32 [T,E]
//   2: router_indices (unused)    3: gate_up_proj fp32 [E,D,2F]
//   4: down_proj fp32 [E,F,D]     out: fp32 [T,D]
// ---------------------------------------------------------------------------
extern "C" void kernel_launch(void* const* d_in, const int* in_sizes, int n_in,
                              void* d_out, int out_size)
{
    const float* X   = (const float*)d_in[0];
    const float* RW  = (const float*)d_in[1];
    const float* Wgu = (const float*)d_in[3];
    const float* Wdn = (const float*)d_in[4];
    float* Out = (float*)d_out;

    cudaFuncSetAttribute(moe_gemm1, cudaFuncAttributeMaxDynamicSharedMemorySize, SMEM_BYTES);
    cudaFuncSetAttribute(moe_gemm2, cudaFuncAttributeMaxDynamicSharedMemorySize, SMEM_BYTES);

    moe_gemm1<<<dim3(kT / BM, k2F / BN, kE), 256, SMEM_BYTES>>>(X, Wgu);   // (16,12,32)

    const int actBlocks = (int)(((size_t)kE * kT * kF / 4) / 256);         // 49152
    moe_act<<<actBlocks, 256>>>(RW);

    moe_gemm2<<<dim3(kT / BM, kD / BN), 256, SMEM_BYTES>>>(Wdn, Out);      // (16,16)
}

// round 6
// speedup vs baseline: 1.9947x; 1.0982x over previous
#include <cuda_runtime.h>
#include <cstdint>

// ---------------------------------------------------------------------------
// Problem constants
// ---------------------------------------------------------------------------
constexpr int kE = 32, kD = 2048, kF = 768, kT = 2048;
constexpr int k2F = 2 * kF;                       // 1536

constexpr int BM = 128, BN = 128, BK = 32;
constexpr int STAGES = 3;

// smem geometry (floats).
// A_LD = 40 (== 8 mod 32): LDS.64 A-fragment loads are bank-conflict-free
// per 16-lane wavefront. B_LD = 136 (== 8 mod 32): LDS.32 B loads conflict-free.
constexpr int A_LD = 40, B_LD = 136;
constexpr int A_F = BM * A_LD;                    // 5120
constexpr int B_F = BK * B_LD;                    // 4352
constexpr int STAGE_F = A_F + B_F;                // 9472 floats
constexpr int SMEM_BYTES = STAGES * STAGE_F * 4;  // 113664 B (2 CTA/SM fits 227KB)

// Scratch (device globals; no allocations allowed)
__device__ float g_Xr    [(size_t)kT * kD];        // X, tf32-rounded, k-octet-permuted
__device__ float g_Wgur  [(size_t)kE * kD * k2F];  // Wgu, tf32-rounded
__device__ float g_Wdr   [(size_t)kE * kF * kD];   // Wd,  tf32-rounded
__device__ float g_gateup[(size_t)kE * kT * k2F];  // raw gate_up
__device__ float g_gated [(size_t)kE * kT * kF];   // rw*up*silu(gate), rounded+permuted

// ---------------------------------------------------------------------------
// helpers
// ---------------------------------------------------------------------------
__device__ __forceinline__ uint32_t smem_u32(const void* p) {
    uint32_t a;
    asm("{ .reg .u64 t; cvta.to.shared.u64 t, %1; cvt.u32.u64 %0, t; }"
        : "=r"(a) : "l"(p));
    return a;
}
__device__ __forceinline__ float to_tf32(float x) {
    float r; asm("cvt.rna.tf32.f32 %0, %1;" : "=f"(r) : "f"(x)); return r;
}
__device__ __forceinline__ float4 round4(float4 v) {
    v.x = to_tf32(v.x); v.y = to_tf32(v.y);
    v.z = to_tf32(v.z); v.w = to_tf32(v.w);
    return v;
}
__device__ __forceinline__ void cp16(uint32_t saddr, const float* g) {
    asm volatile("cp.async.cg.shared.global [%0], [%1], 16;" :: "r"(saddr), "l"(g));
}
#define CP_COMMIT() asm volatile("cp.async.commit_group;" ::: "memory")
#define CP_WAIT1()  asm volatile("cp.async.wait_group 1;" ::: "memory")

__device__ __forceinline__ void mma8(float* c, const uint32_t* a, const uint32_t* b) {
    asm volatile(
        "mma.sync.aligned.m16n8k8.row.col.f32.tf32.tf32.f32 "
        "{%0,%1,%2,%3}, {%4,%5,%6,%7}, {%8,%9}, {%0,%1,%2,%3};"
        : "+f"(c[0]), "+f"(c[1]), "+f"(c[2]), "+f"(c[3])
        : "r"(a[0]), "r"(a[1]), "r"(a[2]), "r"(a[3]), "r"(b[0]), "r"(b[1]));
}

// Octet interleave for A-operand storage: orig cols (j, j+4) -> adjacent pair.
// Given o[0..7] (orig order), packed output is (o0,o4,o1,o5) (o2,o6,o3,o7).
__device__ __forceinline__ void perm_store8(float* dst, const float* o) {
    *(float4*)(dst)     = make_float4(o[0], o[4], o[1], o[5]);
    *(float4*)(dst + 4) = make_float4(o[2], o[6], o[3], o[7]);
}

// ---------------------------------------------------------------------------
// Shared GEMM core: C[BMxBN], 8 warps in 2(m) x 4(n), warp tile 64x32.
// A smem [BM][A_LD]: k contiguous, PERMUTED within octets (pre-permuted gmem).
// B smem [BK][B_LD]: n contiguous, original k order.
// All values pre-rounded to tf32 -> raw bits feed mma directly (no cvt).
// ---------------------------------------------------------------------------
struct WarpCtx { int wm, wn, g, tig; };

__device__ __forceinline__ void compute_stage(const float* As, const float* Bs,
                                              const WarpCtx& w, float c[4][4][4]) {
#pragma unroll
    for (int kk = 0; kk < BK; kk += 8) {
        uint32_t a[4][4];
#pragma unroll
        for (int mi = 0; mi < 4; ++mi) {
            const int r = w.wm + 16 * mi + w.g;
            // permuted pair: pos 2*tig holds orig col tig, 2*tig+1 holds tig+4
            const float2 v0 = *(const float2*)&As[r * A_LD + kk + 2 * w.tig];
            const float2 v1 = *(const float2*)&As[(r + 8) * A_LD + kk + 2 * w.tig];
            a[mi][0] = __float_as_uint(v0.x);   // (row g,   k tig)
            a[mi][1] = __float_as_uint(v1.x);   // (row g+8, k tig)
            a[mi][2] = __float_as_uint(v0.y);   // (row g,   k tig+4)
            a[mi][3] = __float_as_uint(v1.y);   // (row g+8, k tig+4)
        }
        uint32_t b[4][2];
#pragma unroll
        for (int nj = 0; nj < 4; ++nj) {
            const int col = w.wn + 8 * nj + w.g;
            b[nj][0] = __float_as_uint(Bs[(kk + w.tig) * B_LD + col]);
            b[nj][1] = __float_as_uint(Bs[(kk + w.tig + 4) * B_LD + col]);
        }
#pragma unroll
        for (int mi = 0; mi < 4; ++mi)
#pragma unroll
            for (int nj = 0; nj < 4; ++nj)
                mma8(c[mi][nj], a[mi], b[nj]);
    }
}

// ---------------------------------------------------------------------------
// Pre-pass kernels
// ---------------------------------------------------------------------------
// X: round to tf32 + octet-permute. One thread per 8 floats.
__global__ __launch_bounds__(256)
void prep_X(const float* __restrict__ X) {
    const size_t idx = (size_t)blockIdx.x * 256 + threadIdx.x;  // T*D/8 threads
    const size_t off = idx * 8;
    float4 x0 = round4(*(const float4*)(X + off));
    float4 x1 = round4(*(const float4*)(X + off + 4));
    float o[8] = { x0.x, x0.y, x0.z, x0.w, x1.x, x1.y, x1.z, x1.w };
    perm_store8(g_Xr + off, o);
}
// Weights: plain tf32 round (no permutation; B operands keep original k order).
__global__ __launch_bounds__(256)
void prep_Wgu(const float* __restrict__ W) {
    const size_t i4 = ((size_t)blockIdx.x * 256 + threadIdx.x) * 4;
    *(float4*)(g_Wgur + i4) = round4(*(const float4*)(W + i4));
}
__global__ __launch_bounds__(256)
void prep_Wd(const float* __restrict__ W) {
    const size_t i4 = ((size_t)blockIdx.x * 256 + threadIdx.x) * 4;
    *(float4*)(g_Wdr + i4) = round4(*(const float4*)(W + i4));
}

// ---------------------------------------------------------------------------
// GEMM1: g_gateup[e][t][n] = Xr[t][:] @ Wgur[e][:][n]
// grid (16, 12, 32), 256 threads
// ---------------------------------------------------------------------------
__global__ __launch_bounds__(256, 2)
void moe_gemm1(const float* __restrict__ dummy) {
    extern __shared__ float sm[];
    const int tid = threadIdx.x;
    const int m0 = blockIdx.x * BM, n0 = blockIdx.y * BN, e = blockIdx.z;
    const float* We = g_Wgur + (size_t)e * kD * k2F;
    const uint32_t sb = smem_u32(sm);

    const int arow = tid >> 1, acol = (tid & 1) * 16;
    const int brow = tid >> 3, bcol = (tid & 7) * 16;
    const float* gA = g_Xr + (size_t)(m0 + arow) * kD + acol;
    const float* gB = We + (size_t)brow * k2F + n0 + bcol;

    const WarpCtx w = { ((tid >> 5) >> 2) * 64, ((tid >> 5) & 3) * 32,
                        (tid & 31) >> 2, tid & 3 };

    float c[4][4][4];
#pragma unroll
    for (int i = 0; i < 4; ++i)
#pragma unroll
        for (int j = 0; j < 4; ++j)
#pragma unroll
            for (int q = 0; q < 4; ++q) c[i][j][q] = 0.0f;

    constexpr int ITERS = kD / BK;   // 64

    auto issue = [&](int it) {
        const int s = it % STAGES;
        const uint32_t sa = sb + (s * STAGE_F) * 4;
        const uint32_t sbb = sa + A_F * 4;
        const int k0 = it * BK;
#pragma unroll
        for (int q = 0; q < 4; ++q)
            cp16(sa + (arow * A_LD + acol + q * 4) * 4, gA + k0 + q * 4);
#pragma unroll
        for (int q = 0; q < 4; ++q)
            cp16(sbb + (brow * B_LD + bcol + q * 4) * 4,
                 gB + (size_t)k0 * k2F + q * 4);
    };

    issue(0); CP_COMMIT();
    issue(1); CP_COMMIT();

    for (int it = 0; it < ITERS; ++it) {
        CP_WAIT1();
        __syncthreads();
        if (it + 2 < ITERS) issue(it + 2);
        CP_COMMIT();
        const float* As = sm + (it % STAGES) * STAGE_F;
        compute_stage(As, As + A_F, w, c);
        __syncthreads();
    }

    float* Cp = g_gateup + ((size_t)e * kT + m0) * k2F + n0;
#pragma unroll
    for (int mi = 0; mi < 4; ++mi)
#pragma unroll
        for (int nj = 0; nj < 4; ++nj) {
            const int r0 = w.wm + 16 * mi + w.g;
            const int cc = w.wn + 8 * nj + 2 * w.tig;
            *(float2*)(Cp + (size_t)r0 * k2F + cc) = make_float2(c[mi][nj][0], c[mi][nj][1]);
            *(float2*)(Cp + (size_t)(r0 + 8) * k2F + cc) = make_float2(c[mi][nj][2], c[mi][nj][3]);
        }
}

// ---------------------------------------------------------------------------
// Act: g_gated[e][t][f] = round_tf32(rw[t][e] * up * silu(gate)), f-octet-permuted
// One thread per 8 f's.
// ---------------------------------------------------------------------------
__global__ __launch_bounds__(256)
void moe_act(const float* __restrict__ RW) {
    constexpr int NO = kF / 8;                         // 96 octets per (e,t)
    const size_t idx = (size_t)blockIdx.x * 256 + threadIdx.x;
    const int oct = (int)(idx % NO);
    const size_t rest = idx / NO;
    const int t = (int)(rest % kT);
    const int e = (int)(rest / kT);

    const float rw = RW[(size_t)t * kE + e];
    const float* base = g_gateup + ((size_t)e * kT + t) * k2F + oct * 8;
    const float4 g0 = *(const float4*)(base);
    const float4 g1 = *(const float4*)(base + 4);
    const float4 u0 = *(const float4*)(base + kF);
    const float4 u1 = *(const float4*)(base + kF + 4);

    float o[8];
    const float gt[8] = { g0.x, g0.y, g0.z, g0.w, g1.x, g1.y, g1.z, g1.w };
    const float up[8] = { u0.x, u0.y, u0.z, u0.w, u1.x, u1.y, u1.z, u1.w };
#pragma unroll
    for (int j = 0; j < 8; ++j)
        o[j] = to_tf32(rw * up[j] * (gt[j] / (1.0f + __expf(-gt[j]))));

    perm_store8(g_gated + ((size_t)e * kT + t) * kF + oct * 8, o);
}

// ---------------------------------------------------------------------------
// GEMM2: Out[t][d] = sum_{e,f} g_gated[e][t][f] * Wdr[e][f][d]
// grid (16, 16), 256 threads, K = E*F = 24576 (768 iters)
// ---------------------------------------------------------------------------
__global__ __launch_bounds__(256, 2)
void moe_gemm2(float* __restrict__ Out) {
    extern __shared__ float sm[];
    const int tid = threadIdx.x;
    const int m0 = blockIdx.x * BM, n0 = blockIdx.y * BN;
    const uint32_t sb = smem_u32(sm);

    const int arow = tid >> 1, acol = (tid & 1) * 16;
    const int brow = tid >> 3, bcol = (tid & 7) * 16;

    const WarpCtx w = { ((tid >> 5) >> 2) * 64, ((tid >> 5) & 3) * 32,
                        (tid & 31) >> 2, tid & 3 };

    float c[4][4][4];
#pragma unroll
    for (int i = 0; i < 4; ++i)
#pragma unroll
        for (int j = 0; j < 4; ++j)
#pragma unroll
            for (int q = 0; q < 4; ++q) c[i][j][q] = 0.0f;

    constexpr int ITERS = kE * kF / BK;   // 768
    constexpr int IPEX  = kF / BK;        // 24

    auto issue = [&](int it) {
        const int s = it % STAGES;
        const uint32_t sa = sb + (s * STAGE_F) * 4;
        const uint32_t sbb = sa + A_F * 4;
        const int e   = it / IPEX;
        const int kin = (it - e * IPEX) * BK;
        const float* gA = g_gated + ((size_t)e * kT + m0 + arow) * kF + kin + acol;
        const float* gB = g_Wdr + ((size_t)e * kF + kin + brow) * kD + n0 + bcol;
#pragma unroll
        for (int q = 0; q < 4; ++q)
            cp16(sa + (arow * A_LD + acol + q * 4) * 4, gA + q * 4);
#pragma unroll
        for (int q = 0; q < 4; ++q)
            cp16(sbb + (brow * B_LD + bcol + q * 4) * 4, gB + q * 4);
    };

    issue(0); CP_COMMIT();
    issue(1); CP_COMMIT();

    for (int it = 0; it < ITERS; ++it) {
        CP_WAIT1();
        __syncthreads();
        if (it + 2 < ITERS) issue(it + 2);
        CP_COMMIT();
        const float* As = sm + (it % STAGES) * STAGE_F;
        compute_stage(As, As + A_F, w, c);
        __syncthreads();
    }

    float* Cp = Out + (size_t)m0 * kD + n0;
#pragma unroll
    for (int mi = 0; mi < 4; ++mi)
#pragma unroll
        for (int nj = 0; nj < 4; ++nj) {
            const int r0 = w.wm + 16 * mi + w.g;
            const int cc = w.wn + 8 * nj + 2 * w.tig;
            *(float2*)(Cp + (size_t)r0 * kD + cc) = make_float2(c[mi][nj][0], c[mi][nj][1]);
            *(float2*)(Cp + (size_t)(r0 + 8) * kD + cc) = make_float2(c[mi][nj][2], c[mi][nj][3]);
        }
}

// ---------------------------------------------------------------------------
// kernel_launch
//   0: hidden_states fp32 [T,D]   1: routing_weights fp32 [T,E]
//   2: router_indices (unused)    3: gate_up_proj fp32 [E,D,2F]
//   4: down_proj fp32 [E,F,D]     out: fp32 [T,D]
// ---------------------------------------------------------------------------
extern "C" void kernel_launch(void* const* d_in, const int* in_sizes, int n_in,
                              void* d_out, int out_size)
{
    const float* X   = (const float*)d_in[0];
    const float* RW  = (const float*)d_in[1];
    const float* Wgu = (const float*)d_in[3];
    const float* Wdn = (const float*)d_in[4];
    float* Out = (float*)d_out;

    cudaFuncSetAttribute(moe_gemm1, cudaFuncAttributeMaxDynamicSharedMemorySize, SMEM_BYTES);
    cudaFuncSetAttribute(moe_gemm2, cudaFuncAttributeMaxDynamicSharedMemorySize, SMEM_BYTES);

    // Pre-round (and permute X) into scratch
    prep_X<<<(int)(((size_t)kT * kD / 8) / 256), 256>>>(X);                   // 2048 blocks
    prep_Wgu<<<(int)(((size_t)kE * kD * k2F / 4) / 256), 256>>>(Wgu);         // 98304
    prep_Wd<<<(int)(((size_t)kE * kF * kD / 4) / 256), 256>>>(Wdn);           // 49152

    moe_gemm1<<<dim3(kT / BM, k2F / BN, kE), 256, SMEM_BYTES>>>(nullptr);     // (16,12,32)

    const int actBlocks = (int)(((size_t)kE * kT * (kF / 8)) / 256);          // 24576
    moe_act<<<actBlocks, 256>>>(RW);

    moe_gemm2<<<dim3(kT / BM, kD / BN), 256, SMEM_BYTES>>>(Out);              // (16,16)
}